// round 5
// baseline (speedup 1.0000x reference)
#include <cuda_runtime.h>
#include <cstdint>
#include <math.h>

// T=512, B=64, E=512, H=1024, V=256, G=4H=4096

// ---------------- device scratch ----------------
__device__ float g_xg[(size_t)32768 * 4096];      // X @ Wx + b, all steps
__device__ float g_hall[(size_t)513 * 64 * 1024]; // h_0..h_512
__device__ float g_wx4[(size_t)512 * 4096];       // packed x-part of gate weights
__device__ float g_b4[4096];                      // packed gate biases
__device__ unsigned g_cnt;
__device__ unsigned g_gen;

// ---------------- helpers ----------------
__device__ __forceinline__ uint32_t f2tf(float x) {
    uint32_t r;
    asm("cvt.rna.tf32.f32 %0, %1;" : "=r"(r) : "f"(x));
    return r;
}
__device__ __forceinline__ float sigf(float x) { return 1.0f / (1.0f + expf(-x)); }

__device__ __forceinline__ void mma8(float* d, const uint32_t* a, const uint32_t* b) {
    asm volatile(
        "mma.sync.aligned.m16n8k8.row.col.f32.tf32.tf32.f32 "
        "{%0,%1,%2,%3}, {%4,%5,%6,%7}, {%8,%9}, {%0,%1,%2,%3};"
        : "+f"(d[0]), "+f"(d[1]), "+f"(d[2]), "+f"(d[3])
        : "r"(a[0]), "r"(a[1]), "r"(a[2]), "r"(a[3]), "r"(b[0]), "r"(b[1]));
}

// Grid barrier: all 128 CTAs co-resident (1 CTA/SM via 172KB smem, 128 < 148 SMs).
// Release side: EVERY thread fences before syncthreads so all h-stores are
// device-visible before thread 0 publishes the arrival. Acquire side: fence
// after the spin before any thread reads peer data.
__device__ __forceinline__ void gridbar(unsigned target, unsigned nc) {
    __threadfence();
    __syncthreads();
    if (threadIdx.x == 0) {
        unsigned a = atomicAdd(&g_cnt, 1);
        if (a == target * nc - 1) {
            atomicExch(&g_gen, target);
        } else {
            while (*((volatile unsigned*)&g_gen) < target) { __nanosleep(64); }
        }
        __threadfence();
    }
    __syncthreads();
}

// ---------------- pack: gate-major x-weights + biases; reset barrier ----------------
__global__ void pack_kernel(const float* __restrict__ Wf, const float* __restrict__ Wi,
                            const float* __restrict__ Wo, const float* __restrict__ Wc,
                            const float* __restrict__ bf, const float* __restrict__ bi,
                            const float* __restrict__ bo, const float* __restrict__ bc) {
    int idx = blockIdx.x * 256 + threadIdx.x;
    if (idx == 0) { g_cnt = 0; g_gen = 0; }
    if (idx < 512 * 4096) {
        int k = idx >> 12, n = idx & 4095, g = n >> 10, j = n & 1023;
        const float* W = (g == 0) ? Wf : (g == 1) ? Wi : (g == 2) ? Wo : Wc;
        g_wx4[idx] = W[(size_t)k * 1024 + j];
    }
    if (idx < 4096) {
        int g = idx >> 10, j = idx & 1023;
        const float* bb = (g == 0) ? bf : (g == 1) ? bi : (g == 2) ? bo : bc;
        g_b4[idx] = bb[j];
    }
}

// ---------------- generic tf32 GEMM: C[M,N] = A[M,K] @ B[K,N] + bias ----------------
// CTA tile 128x64, K-chunk 32, 256 threads (4m x 2n warps), double-buffered SMEM.
// M % 128 == 0 (grid.y), N % 64 == 0 (grid.x), K % 32 == 0.
__global__ __launch_bounds__(256) void gemm_tf32_kernel(
    const float* __restrict__ A, int lda,
    const float* __restrict__ Bm, int ldb,
    const float* __restrict__ bias,
    float* __restrict__ C, int ldc, int K) {
    extern __shared__ float sm[];
    float* As = sm;                // [2][128][36]
    float* Bs = sm + 2 * 128 * 36; // [2][32][72]
    const int tid = threadIdx.x;
    const int w = tid >> 5, lane = tid & 31, gq = lane >> 2, tg = lane & 3;
    const int wm = w & 3, wn = w >> 2;
    const size_t Mbase = (size_t)blockIdx.y * 128;
    const int Nbase = blockIdx.x * 64;

    int aRow[4], aF4[4];
#pragma unroll
    for (int i = 0; i < 4; i++) { int id = tid + i * 256; aRow[i] = id >> 3; aF4[i] = (id & 7) * 4; }
    int bRow[2], bF4[2];
#pragma unroll
    for (int i = 0; i < 2; i++) { int id = tid + i * 256; bRow[i] = id >> 4; bF4[i] = (id & 15) * 4; }

    float4 ar[4], br[2];
    auto LDG = [&](int kc) {
#pragma unroll
        for (int i = 0; i < 4; i++)
            ar[i] = *(const float4*)(A + (Mbase + aRow[i]) * lda + kc + aF4[i]);
#pragma unroll
        for (int i = 0; i < 2; i++)
            br[i] = *(const float4*)(Bm + (size_t)(kc + bRow[i]) * ldb + Nbase + bF4[i]);
    };
    auto STS = [&](int buf) {
        float* Ab = As + buf * 128 * 36;
        float* Bb = Bs + buf * 32 * 72;
#pragma unroll
        for (int i = 0; i < 4; i++) {
            float* p = Ab + aRow[i] * 36 + aF4[i];
            p[0] = __uint_as_float(f2tf(ar[i].x)); p[1] = __uint_as_float(f2tf(ar[i].y));
            p[2] = __uint_as_float(f2tf(ar[i].z)); p[3] = __uint_as_float(f2tf(ar[i].w));
        }
#pragma unroll
        for (int i = 0; i < 2; i++) {
            float* p = Bb + bRow[i] * 72 + bF4[i];
            p[0] = __uint_as_float(f2tf(br[i].x)); p[1] = __uint_as_float(f2tf(br[i].y));
            p[2] = __uint_as_float(f2tf(br[i].z)); p[3] = __uint_as_float(f2tf(br[i].w));
        }
    };

    float acc[2][4][4];
#pragma unroll
    for (int mt = 0; mt < 2; mt++)
#pragma unroll
        for (int nt = 0; nt < 4; nt++)
#pragma unroll
            for (int q = 0; q < 4; q++) acc[mt][nt][q] = 0.0f;

    LDG(0); STS(0); __syncthreads();
    const int nch = K >> 5;
    for (int c = 0; c < nch; c++) {
        if (c + 1 < nch) LDG((c + 1) << 5);
        const float* Ab = As + (c & 1) * 128 * 36;
        const float* Bb = Bs + (c & 1) * 32 * 72;
#pragma unroll
        for (int kt = 0; kt < 4; kt++) {
            const int k0 = kt * 8;
            uint32_t afr[2][4];
#pragma unroll
            for (int mt = 0; mt < 2; mt++) {
                const int mb = wm * 32 + mt * 16;
                afr[mt][0] = __float_as_uint(Ab[(mb + gq) * 36 + k0 + tg]);
                afr[mt][1] = __float_as_uint(Ab[(mb + gq + 8) * 36 + k0 + tg]);
                afr[mt][2] = __float_as_uint(Ab[(mb + gq) * 36 + k0 + tg + 4]);
                afr[mt][3] = __float_as_uint(Ab[(mb + gq + 8) * 36 + k0 + tg + 4]);
            }
            uint32_t bfr[4][2];
#pragma unroll
            for (int nt = 0; nt < 4; nt++) {
                const int nb = wn * 32 + nt * 8;
                bfr[nt][0] = __float_as_uint(Bb[(k0 + tg) * 72 + nb + gq]);
                bfr[nt][1] = __float_as_uint(Bb[(k0 + tg + 4) * 72 + nb + gq]);
            }
#pragma unroll
            for (int mt = 0; mt < 2; mt++)
#pragma unroll
                for (int nt = 0; nt < 4; nt++) mma8(acc[mt][nt], afr[mt], bfr[nt]);
        }
        if (c + 1 < nch) STS((c + 1) & 1);
        __syncthreads();
    }

#pragma unroll
    for (int mt = 0; mt < 2; mt++) {
#pragma unroll
        for (int nt = 0; nt < 4; nt++) {
            const size_t row = Mbase + wm * 32 + mt * 16 + gq;
            const int col = Nbase + wn * 32 + nt * 8 + tg * 2;
            const float b0 = bias[col], b1 = bias[col + 1];
            C[row * ldc + col]           = acc[mt][nt][0] + b0;
            C[row * ldc + col + 1]       = acc[mt][nt][1] + b1;
            C[(row + 8) * ldc + col]     = acc[mt][nt][2] + b0;
            C[(row + 8) * ldc + col + 1] = acc[mt][nt][3] + b1;
        }
    }
}

// ---------------- persistent LSTM recurrence ----------------
// 128 CTAs x 256 thr. CTA b owns h-cols [8b,8b+8) => gate cols {g*1024+8b..+7}.
// Wh slice in SMEM in mma B-fragment order; cell slice in SMEM fp32.
__global__ __launch_bounds__(256, 1) void lstm_kernel(
    const float* __restrict__ h0, const float* __restrict__ c0,
    const float* __restrict__ Wf, const float* __restrict__ Wi,
    const float* __restrict__ Wo, const float* __restrict__ Wc,
    float* __restrict__ out_tail) {
    extern __shared__ float sm[];
    float* wfr = sm;                 // 32768: [kt(128)][gate(4)][half(2)][lane(32)]
    float* hs  = sm + 32768;         // 2 x [64][68] h chunk staging
    float* Ps  = hs + 2 * 4352;      // [64][33] pre-activations
    float* cs  = Ps + 2112;          // [64][8] cell state
    const int tid = threadIdx.x;
    const int w = tid >> 5, lane = tid & 31, gq = lane >> 2, tg = lane & 3;
    const int wm = w & 3, wn = w >> 2;
    const int j0 = blockIdx.x * 8;
    const unsigned NC = 128u;

    const float* Wg[4] = {Wf, Wi, Wo, Wc};
    for (int idx = tid; idx < 32768; idx += 256) {
        int l = idx & 31, half = (idx >> 5) & 1, nt = (idx >> 6) & 3, kt = idx >> 8;
        int k = kt * 8 + (l & 3) + half * 4;
        int jl = l >> 2;
        float v = Wg[nt][(size_t)(512 + k) * 1024 + j0 + jl];
        wfr[idx] = __uint_as_float(f2tf(v));
    }
    for (int idx = tid; idx < 512; idx += 256) {
        int r = idx >> 3, jl = idx & 7;
        cs[idx] = c0[r * 1024 + j0 + jl];
        g_hall[(size_t)r * 1024 + j0 + jl] = h0[r * 1024 + j0 + jl];
    }
    __syncthreads();
    gridbar(1, NC);

    int hRow[4], hF4[4];
#pragma unroll
    for (int i = 0; i < 4; i++) { int id = tid + i * 256; hRow[i] = id >> 4; hF4[i] = (id & 15) * 4; }

    for (int s = 0; s < 512; s++) {
        const float* hp = g_hall + (size_t)s * 65536;
        float4 hr[4];
        auto LDGH = [&](int ch) {
#pragma unroll
            for (int i = 0; i < 4; i++)
                hr[i] = *(const float4*)(hp + (size_t)hRow[i] * 1024 + ch * 64 + hF4[i]);
        };
        auto STSH = [&](int buf) {
            float* hb = hs + buf * 4352;
#pragma unroll
            for (int i = 0; i < 4; i++) {
                float* p = hb + hRow[i] * 68 + hF4[i];
                p[0] = __uint_as_float(f2tf(hr[i].x)); p[1] = __uint_as_float(f2tf(hr[i].y));
                p[2] = __uint_as_float(f2tf(hr[i].z)); p[3] = __uint_as_float(f2tf(hr[i].w));
            }
        };

        float acc[2][4];
#pragma unroll
        for (int n2 = 0; n2 < 2; n2++)
#pragma unroll
            for (int q = 0; q < 4; q++) acc[n2][q] = 0.0f;

        LDGH(0); STSH(0); __syncthreads();
        for (int ch = 0; ch < 16; ch++) {
            if (ch + 1 < 16) LDGH(ch + 1);
            const float* hb = hs + (ch & 1) * 4352;
#pragma unroll
            for (int ktl = 0; ktl < 8; ktl++) {
                const int k0 = ktl * 8;
                const int kt = ch * 8 + ktl;
                uint32_t af[4];
                const int mb = wm * 16;
                af[0] = __float_as_uint(hb[(mb + gq) * 68 + k0 + tg]);
                af[1] = __float_as_uint(hb[(mb + gq + 8) * 68 + k0 + tg]);
                af[2] = __float_as_uint(hb[(mb + gq) * 68 + k0 + tg + 4]);
                af[3] = __float_as_uint(hb[(mb + gq + 8) * 68 + k0 + tg + 4]);
#pragma unroll
                for (int nt2 = 0; nt2 < 2; nt2++) {
                    const int ntg = wn * 2 + nt2;
                    const float* wp = wfr + ((size_t)kt * 4 + ntg) * 64;
                    uint32_t bf2[2] = {__float_as_uint(wp[lane]), __float_as_uint(wp[32 + lane])};
                    mma8(acc[nt2], af, bf2);
                }
            }
            if (ch + 1 < 16) STSH((ch + 1) & 1);
            __syncthreads();
        }

        // add precomputed x-part (bias already folded in) -> Ps
        const float* xgp = g_xg + (size_t)s * 64 * 4096;
#pragma unroll
        for (int nt2 = 0; nt2 < 2; nt2++) {
            const int ntg = wn * 2 + nt2;
            const int ncol = ntg * 8 + tg * 2;
            const int gcol = ntg * 1024 + j0 + tg * 2;
            const int r0 = wm * 16 + gq;
            Ps[r0 * 33 + ncol]           = acc[nt2][0] + xgp[(size_t)r0 * 4096 + gcol];
            Ps[r0 * 33 + ncol + 1]       = acc[nt2][1] + xgp[(size_t)r0 * 4096 + gcol + 1];
            Ps[(r0 + 8) * 33 + ncol]     = acc[nt2][2] + xgp[(size_t)(r0 + 8) * 4096 + gcol];
            Ps[(r0 + 8) * 33 + ncol + 1] = acc[nt2][3] + xgp[(size_t)(r0 + 8) * 4096 + gcol + 1];
        }
        __syncthreads();

        float* hout = g_hall + (size_t)(s + 1) * 65536;
#pragma unroll
        for (int q = 0; q < 2; q++) {
            const int pos = tid + q * 256;
            const int r = pos >> 3, jl = pos & 7;
            const float f  = sigf(Ps[r * 33 + jl]);
            const float i  = sigf(Ps[r * 33 + 8 + jl]);
            const float o  = sigf(Ps[r * 33 + 16 + jl]);
            const float cc = tanhf(Ps[r * 33 + 24 + jl]);
            const float cv = f * cs[pos] + i * cc;
            cs[pos] = cv;
            const float hv = o * tanhf(cv);
            hout[(size_t)r * 1024 + j0 + jl] = hv;
            if (s == 511) out_tail[(size_t)r * 1024 + j0 + jl] = hv;
        }
        gridbar((unsigned)(s + 2), NC);
    }

    // final cell state
    for (int idx = tid; idx < 512; idx += 256) {
        int r = idx >> 3, jl = idx & 7;
        out_tail[65536 + (size_t)r * 1024 + j0 + jl] = cs[idx];
    }
}

extern "C" void kernel_launch(void* const* d_in, const int* in_sizes, int n_in,
                              void* d_out, int out_size) {
    (void)in_sizes; (void)n_in; (void)out_size;
    const float* input_seq = (const float*)d_in[0];
    const float* hidden    = (const float*)d_in[1];
    const float* cell      = (const float*)d_in[2];
    const float* Wf = (const float*)d_in[3];
    const float* bf = (const float*)d_in[4];
    const float* Wi = (const float*)d_in[5];
    const float* bi = (const float*)d_in[6];
    const float* Wo = (const float*)d_in[7];
    const float* bo = (const float*)d_in[8];
    const float* Wc = (const float*)d_in[9];
    const float* bc = (const float*)d_in[10];
    const float* Wout = (const float*)d_in[11];
    const float* bout = (const float*)d_in[12];
    float* out = (float*)d_out;

    void *p_wx4, *p_b4, *p_xg, *p_hall;
    cudaGetSymbolAddress(&p_wx4, g_wx4);
    cudaGetSymbolAddress(&p_b4, g_b4);
    cudaGetSymbolAddress(&p_xg, g_xg);
    cudaGetSymbolAddress(&p_hall, g_hall);

    cudaFuncSetAttribute(gemm_tf32_kernel, cudaFuncAttributeMaxDynamicSharedMemorySize, 55296);
    cudaFuncSetAttribute(lstm_kernel, cudaFuncAttributeMaxDynamicSharedMemorySize, 176384);

    // 1) pack weights/biases, reset barrier
    pack_kernel<<<8192, 256>>>(Wf, Wi, Wo, Wc, bf, bi, bo, bc);

    // 2) precompute x-side gate pre-activations: [32768,4096]
    {
        dim3 grid(4096 / 64, 32768 / 128);
        gemm_tf32_kernel<<<grid, 256, 55296>>>(
            input_seq, 512, (const float*)p_wx4, 4096, (const float*)p_b4,
            (float*)p_xg, 4096, 512);
    }

    // 3) sequential recurrence (persistent, grid barrier per step)
    lstm_kernel<<<128, 256, 176384>>>(hidden, cell, Wf, Wi, Wo, Wc,
                                      out + (size_t)512 * 64 * 256);

    // 4) output projection: out_seq[t,b,:] = h_{t+1}[b,:] @ Wout + bout
    {
        dim3 grid(256 / 64, 32768 / 128);
        gemm_tf32_kernel<<<grid, 256, 55296>>>(
            (const float*)p_hall + 65536, 1024, Wout, 256, bout,
            out, 256, 1024);
    }
}